// round 15
// baseline (speedup 1.0000x reference)
#include <cuda_runtime.h>
#include <cstddef>

#define NS    31
#define KC    64
#define HW    128
#define IMG   (HW*HW)        /* 16384  */
#define CHW   (KC*IMG)       /* 1048576 */
#define LAM   0.1f
#define EPS_BN 1e-5f

#define TSTR   76            /* smem tile row stride (floats): 72 data + 4 pad */
#define TWORDS (38*TSTR)     /* 2888 floats per tile buffer */
#define NF4    684           /* 38 rows * 18 float4 per row */

/* convz dynamic smem: 6 input bufs + 6 weight bufs + reduction scratch */
#define CONVZ_SIN_F   (6*TWORDS)          /* 17328 floats */
#define CONVZ_SW_F    (6*392)             /*  2352 floats */
#define CONVZ_SRED_F  (128)
#define CONVZ_SMEM_B  ((CONVZ_SIN_F + CONVZ_SW_F + CONVZ_SRED_F) * 4)  /* 79232 B */

// ---------------- scratch (device globals: no allocations allowed) ----------
__device__ float g_res  [NS*IMG];     // residual, 2 MB
__device__ float g_tmp  [NS*CHW];     // tmp sparse code, 130 MB
__device__ float g_zpre [NS*CHW];     // gate pre-activation, 130 MB
__device__ float g_psum [NS*KC*8];    // per-tile partial sums (deterministic BN)
__device__ float g_psq  [NS*KC*8];
__device__ float g_outsc[NS*IMG];     // fallback output scratch
__device__ float g_cscsc[NS*CHW];     // fallback csc scratch

// ---------------- f32x2 packed helpers (FFMA2 path, sm_100+) ----------------
__device__ __forceinline__ unsigned long long pack2(float lo, float hi) {
    unsigned long long r;
    asm("mov.b64 %0, {%1, %2};" : "=l"(r)
        : "r"(__float_as_uint(lo)), "r"(__float_as_uint(hi)));
    return r;
}
__device__ __forceinline__ void unpack2(unsigned long long v, float& lo, float& hi) {
    unsigned int a, b;
    asm("mov.b64 {%0, %1}, %2;" : "=r"(a), "=r"(b) : "l"(v));
    lo = __uint_as_float(a);
    hi = __uint_as_float(b);
}
__device__ __forceinline__ unsigned long long ffma2(unsigned long long a,
                                                    unsigned long long b,
                                                    unsigned long long c) {
    unsigned long long d;
    asm("fma.rn.f32x2 %0, %1, %2, %3;" : "=l"(d) : "l"(a), "l"(b), "l"(c));
    return d;
}

__device__ __forceinline__ float softshrink_f(float x) {
    float a = fabsf(x) - LAM;
    a = a > 0.f ? a : 0.f;
    return copysignf(a, x);
}

// input-tile load-slot precompute (shared by convz / conv64to1)
// 16B granules over a [38 x 72] halo starting at (y0-3, x0-4); OOB -> zero fill
__device__ __forceinline__ void tile_slots(int tid, int x0, int y0,
                                           int soff[3], unsigned doff[3]) {
#pragma unroll
    for (int k = 0; k < 3; k++) {
        int i = tid + k * 256;
        if (i < NF4) {
            int r = i / 18, c = i - r * 18;
            int gy  = y0 - 3 + r;
            int gx0 = x0 - 4 + c * 4;
            bool ok = ((unsigned)gy < 128u) & ((unsigned)gx0 < 125u);
            soff[k] = ok ? (gy * 128 + gx0) : -1;
            doff[k] = (unsigned)(r * TSTR + c * 4) * 4u;
        } else {
            soff[k] = -1;
            doff[k] = 0xffffffffu;
        }
    }
}

// one input-channel convolution step (7x7, 8 oc packed as 4 f32x2, 8 px).
__device__ __forceinline__ void convz_ic_body(const float* __restrict__ bin,
                                              const float* __restrict__ bwm,
                                              int ty, int tx,
                                              unsigned long long acc[8][4]) {
#pragma unroll
    for (int ky = 0; ky < 7; ky++) {
        const float4* rp = (const float4*)&bin[(ty + ky) * TSTR + tx * 8];
        float4 a0 = rp[0], a1 = rp[1], a2 = rp[2], a3 = rp[3];
        float row[16];
        row[0]=a0.x; row[1]=a0.y; row[2]=a0.z; row[3]=a0.w;
        row[4]=a1.x; row[5]=a1.y; row[6]=a1.z; row[7]=a1.w;
        row[8]=a2.x; row[9]=a2.y; row[10]=a2.z; row[11]=a2.w;
        row[12]=a3.x; row[13]=a3.y; row[14]=a3.z; row[15]=a3.w;
        unsigned long long xb[14];
#pragma unroll
        for (int i = 0; i < 14; i++) xb[i] = pack2(row[i + 1], row[i + 1]);
#pragma unroll
        for (int kx = 0; kx < 7; kx++) {
            const ulonglong2* wq = (const ulonglong2*)&bwm[(ky * 7 + kx) * 8];
            ulonglong2 q0 = wq[0];
            ulonglong2 q1 = wq[1];
#pragma unroll
            for (int px = 0; px < 8; px++) {
                unsigned long long p2 = xb[kx + px];   // == row[kx+px+1] x2
                acc[px][0] = ffma2(q0.x, p2, acc[px][0]);
                acc[px][1] = ffma2(q0.y, p2, acc[px][1]);
                acc[px][2] = ffma2(q1.x, p2, acc[px][2]);
                acc[px][3] = ffma2(q1.y, p2, acc[px][3]);
            }
        }
    }
}

// ============================================================================
// conv 64->64 (W_z). Tile 64w x 32h, 8 out-channels per block, 8 px/thread.
// 3-stage x 2-ic cp.async ring (one barrier per 2 channels); FFMA2 inner.
// Epilogue emits zpre (float4 stores) + deterministic BN partial sums.
// grid: (2, 4, NS*8), block: 256, dynamic smem CONVZ_SMEM_B
// ============================================================================
__global__ void __launch_bounds__(256, 2)
convz_kernel(const float* __restrict__ src,   // [NS][KC][IMG]
             const float* __restrict__ Wz,    // [64][64][49] for this layer
             const float* __restrict__ bz,    // [64]
             float* __restrict__ dst)         // [NS][KC][IMG]
{
    extern __shared__ __align__(16) float sdyn[];
    float* s_in  = sdyn;                         // [6][TWORDS]
    float* s_w   = sdyn + CONVZ_SIN_F;           // [6][392]
    float* s_red = s_w + CONVZ_SW_F;             // [8][16]

    const int tid = threadIdx.x;
    const int s   = blockIdx.z >> 3;
    const int ocg = blockIdx.z & 7;
    const int x0  = blockIdx.x * 64;
    const int y0  = blockIdx.y * 32;
    const int tx  = tid & 7;    // col block (8 px wide)
    const int ty  = tid >> 3;   // row 0..31

    const unsigned su_in = (unsigned)__cvta_generic_to_shared(s_in);
    const unsigned su_w  = (unsigned)__cvta_generic_to_shared(s_w);

    int soff[3]; unsigned doff[3];
    tile_slots(tid, x0, y0, soff, doff);

    int wsrc[2]; unsigned wdst[2];
#pragma unroll
    for (int k = 0; k < 2; k++) {
        int i = tid + k * 256;
        if (i < 392) {
            int tap = i >> 3, j = i & 7;
            wsrc[k] = (ocg * 8 + j) * 3136 + tap;   // + ic*49 later
            wdst[k] = (unsigned)(tap * 8 + j) * 4u;
        } else { wsrc[k] = -1; wdst[k] = 0; }
    }

    const float* srcS = src + (size_t)s * CHW;

    unsigned long long acc[8][4];
#pragma unroll
    for (int px = 0; px < 8; px++)
#pragma unroll
        for (int p = 0; p < 4; p++) acc[px][p] = 0ULL;

    // prefetch one stage (2 input channels + their weights), one commit group
    auto prefetch_stage = [&](int st) {
        const int ring = st % 3;
#pragma unroll
        for (int sl = 0; sl < 2; sl++) {
            const int ic = st * 2 + sl;
            unsigned bi = su_in + (unsigned)(ring * 2 + sl) * (TWORDS * 4);
            const float* sp = srcS + ic * IMG;
#pragma unroll
            for (int k = 0; k < 3; k++) {
                if (doff[k] != 0xffffffffu) {
                    int so = soff[k];
                    const float* p = sp + (so < 0 ? 0 : so);
                    int sz = (so < 0) ? 0 : 16;
                    asm volatile("cp.async.cg.shared.global [%0], [%1], 16, %2;"
                                 :: "r"(bi + doff[k]), "l"(p), "r"(sz));
                }
            }
            unsigned bw = su_w + (unsigned)(ring * 2 + sl) * (392 * 4);
#pragma unroll
            for (int k = 0; k < 2; k++) {
                if (wsrc[k] >= 0)
                    asm volatile("cp.async.ca.shared.global [%0], [%1], 4;"
                                 :: "r"(bw + wdst[k]), "l"(Wz + wsrc[k] + ic * 49));
            }
        }
        asm volatile("cp.async.commit_group;");
    };

    prefetch_stage(0);

    for (int st = 0; st < KC / 2; st++) {
        if (st < KC / 2 - 1) {
            prefetch_stage(st + 1);
            asm volatile("cp.async.wait_group 1;");
        } else {
            asm volatile("cp.async.wait_group 0;");
        }
        __syncthreads();

        const int ring = st % 3;
#pragma unroll 1
        for (int sl = 0; sl < 2; sl++) {
            const float* bin = s_in + (size_t)(ring * 2 + sl) * TWORDS;
            const float* bwm = s_w  + (size_t)(ring * 2 + sl) * 392;
            convz_ic_body(bin, bwm, ty, tx, acc);
        }
    }

    // ---- epilogue: float4 zpre stores + deterministic BN partials ----
    const int gy = y0 + ty, gxb = x0 + tx * 8;
    const int warp = tid >> 5, lane = tid & 31;
#pragma unroll
    for (int p = 0; p < 4; p++) {
        int oc0 = ocg * 8 + 2 * p;
        float b0 = bz[oc0], b1 = bz[oc0 + 1];
        float* d0 = dst + ((size_t)s * KC + oc0) * IMG + gy * 128 + gxb;
        float* d1 = d0 + IMG;
        float v0[8], v1[8];
        float s0 = 0.f, s1 = 0.f, q0 = 0.f, q1 = 0.f;
#pragma unroll
        for (int px = 0; px < 8; px++) {
            float u0, u1;
            unpack2(acc[px][p], u0, u1);
            u0 += b0; u1 += b1;
            v0[px] = u0; v1[px] = u1;
            s0 += u0; q0 += u0 * u0;
            s1 += u1; q1 += u1 * u1;
        }
        ((float4*)d0)[0] = make_float4(v0[0], v0[1], v0[2], v0[3]);
        ((float4*)d0)[1] = make_float4(v0[4], v0[5], v0[6], v0[7]);
        ((float4*)d1)[0] = make_float4(v1[0], v1[1], v1[2], v1[3]);
        ((float4*)d1)[1] = make_float4(v1[4], v1[5], v1[6], v1[7]);
#pragma unroll
        for (int o = 16; o; o >>= 1) {
            s0 += __shfl_xor_sync(0xffffffffu, s0, o);
            s1 += __shfl_xor_sync(0xffffffffu, s1, o);
            q0 += __shfl_xor_sync(0xffffffffu, q0, o);
            q1 += __shfl_xor_sync(0xffffffffu, q1, o);
        }
        if (lane == 0) {
            s_red[warp * 16 + p * 4 + 0] = s0;
            s_red[warp * 16 + p * 4 + 1] = s1;
            s_red[warp * 16 + p * 4 + 2] = q0;
            s_red[warp * 16 + p * 4 + 3] = q1;
        }
    }
    __syncthreads();
    if (tid < 16) {
        float t = 0.f;
#pragma unroll
        for (int w = 0; w < 8; w++) t += s_red[w * 16 + tid];
        int p = tid >> 2, j = tid & 3;
        int oc = ocg * 8 + 2 * p + (j & 1);
        int tile = blockIdx.y * 2 + blockIdx.x;           // 0..7
        size_t idx = ((size_t)s * KC + oc) * 8 + tile;
        if (j < 2) g_psum[idx] = t;
        else       g_psq[idx]  = t;
    }
}

// ============================================================================
// conv 1->64 (W_fe / W_enc) fused: out = softshrink(conv(src)+b [+ base])
// Vectorized epilogue: float4 base loads + float4 stores.
// grid: (2, 4, NS*8), block: 256
// ============================================================================
__global__ void __launch_bounds__(256, 2)
conv1to64_kernel(const float* __restrict__ src,   // [NS][IMG]
                 const float* __restrict__ W,     // [64][49]
                 const float* __restrict__ b,     // [64]
                 const float* __restrict__ base,  // [NS][KC][IMG] or null
                 float* __restrict__ dst)         // [NS][KC][IMG]
{
    __shared__ __align__(16) float s_in[38*72];
    __shared__ __align__(16) float s_w [49*8];

    const int tid = threadIdx.x;
    const int s   = blockIdx.z >> 3;
    const int ocg = blockIdx.z & 7;
    const int x0  = blockIdx.x * 64;
    const int y0  = blockIdx.y * 32;
    const int tx  = tid & 7;
    const int ty  = tid >> 3;

    const float* sc = src + (size_t)s * IMG;
    for (int i = tid; i < 38*70; i += 256) {
        int r = i / 70, c = i - r * 70;
        int gy = y0 - 3 + r, gx = x0 - 3 + c;
        float v = 0.f;
        if ((unsigned)gy < 128u && (unsigned)gx < 128u)
            v = __ldg(sc + gy * 128 + gx);
        s_in[r * 72 + c] = v;
    }
    for (int i = tid; i < 392; i += 256) {
        int tap = i >> 3, j = i & 7;
        s_w[tap * 8 + j] = W[(size_t)(ocg * 8 + j) * 49 + tap];
    }
    __syncthreads();

    unsigned long long acc[8][4];
#pragma unroll
    for (int px = 0; px < 8; px++)
#pragma unroll
        for (int p = 0; p < 4; p++) acc[px][p] = 0ULL;

#pragma unroll
    for (int ky = 0; ky < 7; ky++) {
        const float4* rp = (const float4*)&s_in[(ty + ky) * 72 + tx * 8];
        float4 a0 = rp[0], a1 = rp[1], a2 = rp[2], a3 = rp[3];
        float row[16];
        row[0]=a0.x; row[1]=a0.y; row[2]=a0.z; row[3]=a0.w;
        row[4]=a1.x; row[5]=a1.y; row[6]=a1.z; row[7]=a1.w;
        row[8]=a2.x; row[9]=a2.y; row[10]=a2.z; row[11]=a2.w;
        row[12]=a3.x; row[13]=a3.y; row[14]=a3.z; row[15]=a3.w;
        unsigned long long xb[14];
#pragma unroll
        for (int i = 0; i < 14; i++) xb[i] = pack2(row[i], row[i]);
#pragma unroll
        for (int kx = 0; kx < 7; kx++) {
            const ulonglong2* wq = (const ulonglong2*)&s_w[(ky * 7 + kx) * 8];
            ulonglong2 q0 = wq[0];
            ulonglong2 q1 = wq[1];
#pragma unroll
            for (int px = 0; px < 8; px++) {
                unsigned long long p2 = xb[kx + px];
                acc[px][0] = ffma2(q0.x, p2, acc[px][0]);
                acc[px][1] = ffma2(q0.y, p2, acc[px][1]);
                acc[px][2] = ffma2(q1.x, p2, acc[px][2]);
                acc[px][3] = ffma2(q1.y, p2, acc[px][3]);
            }
        }
    }

    const int gy = y0 + ty, gxb = x0 + tx * 8;
#pragma unroll
    for (int p = 0; p < 4; p++) {
        int oc0 = ocg * 8 + 2 * p;
        float b0 = b[oc0], b1 = b[oc0 + 1];
        size_t o0 = ((size_t)s * KC + oc0) * IMG + gy * 128 + gxb;
        float v0[8], v1[8];
#pragma unroll
        for (int px = 0; px < 8; px++) {
            float u0, u1;
            unpack2(acc[px][p], u0, u1);
            v0[px] = u0 + b0;
            v1[px] = u1 + b1;
        }
        if (base) {
            float4 ba0 = ((const float4*)(base + o0))[0];
            float4 ba1 = ((const float4*)(base + o0))[1];
            float4 bb0 = ((const float4*)(base + o0 + IMG))[0];
            float4 bb1 = ((const float4*)(base + o0 + IMG))[1];
            v0[0]+=ba0.x; v0[1]+=ba0.y; v0[2]+=ba0.z; v0[3]+=ba0.w;
            v0[4]+=ba1.x; v0[5]+=ba1.y; v0[6]+=ba1.z; v0[7]+=ba1.w;
            v1[0]+=bb0.x; v1[1]+=bb0.y; v1[2]+=bb0.z; v1[3]+=bb0.w;
            v1[4]+=bb1.x; v1[5]+=bb1.y; v1[6]+=bb1.z; v1[7]+=bb1.w;
        }
#pragma unroll
        for (int px = 0; px < 8; px++) {
            v0[px] = softshrink_f(v0[px]);
            v1[px] = softshrink_f(v1[px]);
        }
        ((float4*)(dst + o0))[0]       = make_float4(v0[0], v0[1], v0[2], v0[3]);
        ((float4*)(dst + o0))[1]       = make_float4(v0[4], v0[5], v0[6], v0[7]);
        ((float4*)(dst + o0 + IMG))[0] = make_float4(v1[0], v1[1], v1[2], v1[3]);
        ((float4*)(dst + o0 + IMG))[1] = make_float4(v1[4], v1[5], v1[6], v1[7]);
    }
}

// ============================================================================
// conv 64->1 (W_dec / W_last), 3-stage cp.async pipeline over input channels.
// Inner loop on f32x2 pixel pairs; weights stored PRE-DUPLICATED in smem
// ([49][2] pairs) so the broadcast w2 comes from one LDS.64 (no pack).
// Vectorized xin/dst epilogue.
// mode 0: dst = xin - (conv(src)+b);  mode 1: dst = conv(src)+b
// grid: (2, 4, NS), block: 256
// ============================================================================
__global__ void __launch_bounds__(256, 2)
conv64to1_kernel(const float* __restrict__ src,  // [NS][KC][IMG]
                 const float* __restrict__ W,    // [64][49]
                 const float* __restrict__ b,    // [1]
                 const float* __restrict__ xin,  // [NS][IMG] (mode 0)
                 float* __restrict__ dst,        // [NS][IMG]
                 int mode)
{
    __shared__ __align__(16) float s_in[3][TWORDS];
    __shared__ __align__(8) float s_w[3][104];   // [49 taps][2 dup] + pad

    const int tid = threadIdx.x;
    const int s   = blockIdx.z;
    const int x0  = blockIdx.x * 64;
    const int y0  = blockIdx.y * 32;
    const int tx  = tid & 7;
    const int ty  = tid >> 3;

    const unsigned su_in = (unsigned)__cvta_generic_to_shared(&s_in[0][0]);

    int soff[3]; unsigned doff[3];
    tile_slots(tid, x0, y0, soff, doff);

    unsigned long long acc2[4];
#pragma unroll
    for (int p = 0; p < 4; p++) acc2[p] = 0ULL;

    const float* srcS = src + (size_t)s * CHW;

    for (int ic = -1; ic < KC; ic++) {
        const int nxt = ic + 1;
        if (nxt < KC) {
            unsigned bi = su_in + (unsigned)(nxt % 3) * (TWORDS * 4);
            const float* sp = srcS + nxt * IMG;
#pragma unroll
            for (int k = 0; k < 3; k++) {
                if (doff[k] != 0xffffffffu) {
                    int so = soff[k];
                    const float* p = sp + (so < 0 ? 0 : so);
                    int sz = (so < 0) ? 0 : 16;
                    asm volatile("cp.async.cg.shared.global [%0], [%1], 16, %2;"
                                 :: "r"(bi + doff[k]), "l"(p), "r"(sz));
                }
            }
            if (tid < 49) {
                // pre-duplicated weight pair; barrier below publishes it
                float w = __ldg(W + nxt * 49 + tid);
                s_w[nxt % 3][tid * 2]     = w;
                s_w[nxt % 3][tid * 2 + 1] = w;
            }
            asm volatile("cp.async.commit_group;");
        }
        if (ic < 0) continue;
        if (nxt < KC) asm volatile("cp.async.wait_group 1;");
        else          asm volatile("cp.async.wait_group 0;");
        __syncthreads();

        const float* bin = &s_in[ic % 3][0];
        const float* bwm = &s_w [ic % 3][0];

#pragma unroll
        for (int ky = 0; ky < 7; ky++) {
            const float4* rp = (const float4*)&bin[(ty + ky) * TSTR + tx * 8];
            float4 a0 = rp[0], a1 = rp[1], a2 = rp[2], a3 = rp[3];
            float row[16];
            row[0]=a0.x; row[1]=a0.y; row[2]=a0.z; row[3]=a0.w;
            row[4]=a1.x; row[5]=a1.y; row[6]=a1.z; row[7]=a1.w;
            row[8]=a2.x; row[9]=a2.y; row[10]=a2.z; row[11]=a2.w;
            row[12]=a3.x; row[13]=a3.y; row[14]=a3.z; row[15]=a3.w;
            unsigned long long xe[7], xo[7];
#pragma unroll
            for (int i = 0; i < 7; i++) {
                xe[i] = pack2(row[2*i],     row[2*i + 1]);
                xo[i] = pack2(row[2*i + 1], row[2*i + 2]);
            }
#pragma unroll
            for (int kx = 0; kx < 7; kx++) {
                unsigned long long w2 =
                    *(const unsigned long long*)&bwm[(ky * 7 + kx) * 2];
#pragma unroll
                for (int p = 0; p < 4; p++) {
                    unsigned long long x = (kx & 1)
                        ? xe[((kx + 1) >> 1) + p]
                        : xo[(kx >> 1) + p];
                    acc2[p] = ffma2(w2, x, acc2[p]);
                }
            }
        }
    }

    const float bv = b[0];
    const int gy = y0 + ty, gxb = x0 + tx * 8;
    const size_t o = (size_t)s * IMG + gy * 128 + gxb;
    float v[8];
#pragma unroll
    for (int p = 0; p < 4; p++) {
        float u0, u1;
        unpack2(acc2[p], u0, u1);
        v[2*p]   = u0 + bv;
        v[2*p+1] = u1 + bv;
    }
    if (mode == 0) {
        float4 xa = ((const float4*)(xin + o))[0];
        float4 xbq = ((const float4*)(xin + o))[1];
        v[0] = xa.x  - v[0]; v[1] = xa.y  - v[1];
        v[2] = xa.z  - v[2]; v[3] = xa.w  - v[3];
        v[4] = xbq.x - v[4]; v[5] = xbq.y - v[5];
        v[6] = xbq.z - v[6]; v[7] = xbq.w - v[7];
    }
    ((float4*)(dst + o))[0] = make_float4(v[0], v[1], v[2], v[3]);
    ((float4*)(dst + o))[1] = make_float4(v[4], v[5], v[6], v[7]);
}

// ============================================================================
// Fused BN-finish + BN-normalize + sigmoid + directional GRU scan.
// float4 per thread, 2-deep software pipeline on the band loop so next
// step's loads issue before this step's sigmoid chain.
// grid: CHW/1024 = 1024, block: 256
// ============================================================================
__global__ void scan_kernel(const float* __restrict__ gamma,
                            const float* __restrict__ beta,
                            float* __restrict__ csc, int fwd)
{
    __shared__ float s_mu[NS], s_rs[NS];

    const int c = (int)(((unsigned)blockIdx.x * 1024u) >> 14);   // block-uniform
    if (threadIdx.x < NS) {
        int s = threadIdx.x;
        size_t base = ((size_t)s * KC + c) * 8;
        float sm = 0.f, sq = 0.f;
#pragma unroll
        for (int t = 0; t < 8; t++) {
            sm += g_psum[base + t];
            sq += g_psq [base + t];
        }
        float mu  = sm * (1.f / IMG);
        float var = sq * (1.f / IMG) - mu * mu;
        s_mu[s] = mu;
        s_rs[s] = rsqrtf(var + EPS_BN);
    }
    __syncthreads();

    const float g  = gamma[c];
    const float be = beta[c];
    const size_t p0 = (size_t)blockIdx.x * 1024 + (size_t)threadIdx.x * 4;

    const int s0   = fwd ? 0 : (NS - 1);
    const int step = fwd ? 1 : -1;

    float4 carry = *(const float4*)(g_tmp + (size_t)s0 * CHW + p0);
    *(float4*)(csc + (size_t)s0 * CHW + p0) = carry;

    // prime the pipeline with step 1's loads
    int s_next = s0 + step;
    float4 zp = *(const float4*)(g_zpre + (size_t)s_next * CHW + p0);
    float4 tm = *(const float4*)(g_tmp  + (size_t)s_next * CHW + p0);

    int s = s_next;
    for (int k = 1; k < NS; k++) {
        const size_t o = (size_t)s * CHW + p0;
        float4 zp_c = zp, tm_c = tm;
        const float mu = s_mu[s], rs = s_rs[s];
        if (k < NS - 1) {
            size_t on = (size_t)(s + step) * CHW + p0;
            zp = *(const float4*)(g_zpre + on);
            tm = *(const float4*)(g_tmp  + on);
        }
        {
            float t = ((zp_c.x - mu) * rs) * g + be;
            float z = __fdividef(1.f, 1.f + __expf(-t));
            carry.x = z * carry.x + (1.f - z) * tm_c.x;
        }
        {
            float t = ((zp_c.y - mu) * rs) * g + be;
            float z = __fdividef(1.f, 1.f + __expf(-t));
            carry.y = z * carry.y + (1.f - z) * tm_c.y;
        }
        {
            float t = ((zp_c.z - mu) * rs) * g + be;
            float z = __fdividef(1.f, 1.f + __expf(-t));
            carry.z = z * carry.z + (1.f - z) * tm_c.z;
        }
        {
            float t = ((zp_c.w - mu) * rs) * g + be;
            float z = __fdividef(1.f, 1.f + __expf(-t));
            carry.w = z * carry.w + (1.f - z) * tm_c.w;
        }
        *(float4*)(csc + o) = carry;
        s += step;
    }
}

// ============================================================================
extern "C" void kernel_launch(void* const* d_in, const int* in_sizes, int n_in,
                              void* d_out, int out_size)
{
    const float* inputs = (const float*)d_in[0];
    const float* W_fe   = (const float*)d_in[1];
    const float* b_fe   = (const float*)d_in[2];
    const float* W_enc  = (const float*)d_in[3];
    const float* b_enc  = (const float*)d_in[4];
    const float* W_dec  = (const float*)d_in[5];
    const float* b_dec  = (const float*)d_in[6];
    const float* W_last = (const float*)d_in[7];
    const float* b_last = (const float*)d_in[8];
    const float* W_z    = (const float*)d_in[9];
    const float* b_z    = (const float*)d_in[10];
    const float* bn_g   = (const float*)d_in[11];
    const float* bn_b   = (const float*)d_in[12];
    (void)in_sizes; (void)n_in;

    // allow >48KB dynamic smem for convz (host attribute set; capture-legal)
    cudaFuncSetAttribute((const void*)convz_kernel,
                         cudaFuncAttributeMaxDynamicSharedMemorySize,
                         CONVZ_SMEM_B);

    float *p_res, *p_tmp, *p_zpre, *p_outsc, *p_cscs;
    cudaGetSymbolAddress((void**)&p_res,   g_res);
    cudaGetSymbolAddress((void**)&p_tmp,   g_tmp);
    cudaGetSymbolAddress((void**)&p_zpre,  g_zpre);
    cudaGetSymbolAddress((void**)&p_outsc, g_outsc);
    cudaGetSymbolAddress((void**)&p_cscs,  g_cscsc);

    const long long CSC_N = (long long)NS * CHW;   // 32,505,856
    const long long OUT_N = (long long)NS * IMG;   //    507,904
    float* csc;
    float* outp;
    if ((long long)out_size >= CSC_N + OUT_N) {
        csc  = (float*)d_out;
        outp = (float*)d_out + CSC_N;
    } else if ((long long)out_size >= CSC_N) {
        csc  = (float*)d_out;
        outp = p_outsc;
    } else {
        csc  = p_cscs;
        outp = (float*)d_out;
    }

    dim3 blk(256);
    dim3 g64(2, 4, NS * 8);
    dim3 g1 (2, 4, NS);

    // csc = softshrink(conv_fe(x) + b_fe)
    conv1to64_kernel<<<g64, blk>>>(inputs, W_fe, b_fe, nullptr, csc);

    for (int it = 0; it < 3; it++) {
        // res = x - (conv_dec(csc) + b_dec)
        conv64to1_kernel<<<g1, blk>>>(csc, W_dec + it * 3136, b_dec + it,
                                      inputs, p_res, 0);
        // tmp = softshrink(csc + conv_enc(res) + b_enc)
        conv1to64_kernel<<<g64, blk>>>(p_res, W_enc + it * 3136,
                                       b_enc + it * 64, csc, p_tmp);
        // zpre = conv_z(tmp) + b_z   (also emits BN partial sums)
        convz_kernel<<<g64, blk, CONVZ_SMEM_B>>>(p_tmp,
                                   W_z + (size_t)it * 64 * 64 * 49,
                                   b_z + it * 64, p_zpre);
        // fused BN-finish + BN + sigmoid + directional scan -> csc
        scan_kernel<<<CHW / 1024, 256>>>(bn_g + it * 64, bn_b + it * 64,
                                         csc, (it % 2 == 0) ? 1 : 0);
    }

    // outputs = conv_last(csc) + b_last
    conv64to1_kernel<<<g1, blk>>>(csc, W_last, b_last, nullptr, outp, 1);
}

// round 16
// speedup vs baseline: 1.0172x; 1.0172x over previous
#include <cuda_runtime.h>
#include <cstddef>

#define NS    31
#define KC    64
#define HW    128
#define IMG   (HW*HW)        /* 16384  */
#define CHW   (KC*IMG)       /* 1048576 */
#define LAM   0.1f
#define EPS_BN 1e-5f

#define TSTR   76            /* smem tile row stride (floats): 72 data + 4 pad */
#define TWORDS (38*TSTR)     /* 2888 floats per tile buffer */
#define NF4    684           /* 38 rows * 18 float4 per row */

/* convz dynamic smem: 6 input bufs + 6 weight bufs + reduction scratch */
#define CONVZ_SIN_F   (6*TWORDS)          /* 17328 floats */
#define CONVZ_SW_F    (6*392)             /*  2352 floats */
#define CONVZ_SRED_F  (128)
#define CONVZ_SMEM_B  ((CONVZ_SIN_F + CONVZ_SW_F + CONVZ_SRED_F) * 4)  /* 79232 B */

// ---------------- scratch (device globals: no allocations allowed) ----------
__device__ float g_res  [NS*IMG];     // residual, 2 MB
__device__ float g_tmp  [NS*CHW];     // tmp sparse code, 130 MB
__device__ float g_zpre [NS*CHW];     // gate pre-activation, 130 MB
__device__ float g_psum [NS*KC*8];    // per-tile partial sums (deterministic BN)
__device__ float g_psq  [NS*KC*8];
__device__ float g_outsc[NS*IMG];     // fallback output scratch
__device__ float g_cscsc[NS*CHW];     // fallback csc scratch

// ---------------- f32x2 packed helpers (FFMA2 path, sm_100+) ----------------
__device__ __forceinline__ unsigned long long pack2(float lo, float hi) {
    unsigned long long r;
    asm("mov.b64 %0, {%1, %2};" : "=l"(r)
        : "r"(__float_as_uint(lo)), "r"(__float_as_uint(hi)));
    return r;
}
__device__ __forceinline__ void unpack2(unsigned long long v, float& lo, float& hi) {
    unsigned int a, b;
    asm("mov.b64 {%0, %1}, %2;" : "=r"(a), "=r"(b) : "l"(v));
    lo = __uint_as_float(a);
    hi = __uint_as_float(b);
}
__device__ __forceinline__ unsigned long long ffma2(unsigned long long a,
                                                    unsigned long long b,
                                                    unsigned long long c) {
    unsigned long long d;
    asm("fma.rn.f32x2 %0, %1, %2, %3;" : "=l"(d) : "l"(a), "l"(b), "l"(c));
    return d;
}

__device__ __forceinline__ float softshrink_f(float x) {
    float a = fabsf(x) - LAM;
    a = a > 0.f ? a : 0.f;
    return copysignf(a, x);
}

// input-tile load-slot precompute (shared by convz / conv64to1 / conv1to64)
// 16B granules over a [38 x 72] halo starting at (y0-3, x0-4); OOB -> zero fill
__device__ __forceinline__ void tile_slots(int tid, int x0, int y0,
                                           int soff[3], unsigned doff[3]) {
#pragma unroll
    for (int k = 0; k < 3; k++) {
        int i = tid + k * 256;
        if (i < NF4) {
            int r = i / 18, c = i - r * 18;
            int gy  = y0 - 3 + r;
            int gx0 = x0 - 4 + c * 4;
            bool ok = ((unsigned)gy < 128u) & ((unsigned)gx0 < 125u);
            soff[k] = ok ? (gy * 128 + gx0) : -1;
            doff[k] = (unsigned)(r * TSTR + c * 4) * 4u;
        } else {
            soff[k] = -1;
            doff[k] = 0xffffffffu;
        }
    }
}

// one input-channel convolution step (7x7, 8 oc packed as 4 f32x2, 8 px).
// bin: TSTR-stride tile with halo at (y0-3, x0-4); bwm: [49 taps][8 oc].
__device__ __forceinline__ void convz_ic_body(const float* __restrict__ bin,
                                              const float* __restrict__ bwm,
                                              int ty, int tx,
                                              unsigned long long acc[8][4]) {
#pragma unroll
    for (int ky = 0; ky < 7; ky++) {
        const float4* rp = (const float4*)&bin[(ty + ky) * TSTR + tx * 8];
        float4 a0 = rp[0], a1 = rp[1], a2 = rp[2], a3 = rp[3];
        float row[16];
        row[0]=a0.x; row[1]=a0.y; row[2]=a0.z; row[3]=a0.w;
        row[4]=a1.x; row[5]=a1.y; row[6]=a1.z; row[7]=a1.w;
        row[8]=a2.x; row[9]=a2.y; row[10]=a2.z; row[11]=a2.w;
        row[12]=a3.x; row[13]=a3.y; row[14]=a3.z; row[15]=a3.w;
        unsigned long long xb[14];
#pragma unroll
        for (int i = 0; i < 14; i++) xb[i] = pack2(row[i + 1], row[i + 1]);
#pragma unroll
        for (int kx = 0; kx < 7; kx++) {
            const ulonglong2* wq = (const ulonglong2*)&bwm[(ky * 7 + kx) * 8];
            ulonglong2 q0 = wq[0];
            ulonglong2 q1 = wq[1];
#pragma unroll
            for (int px = 0; px < 8; px++) {
                unsigned long long p2 = xb[kx + px];   // == row[kx+px+1] x2
                acc[px][0] = ffma2(q0.x, p2, acc[px][0]);
                acc[px][1] = ffma2(q0.y, p2, acc[px][1]);
                acc[px][2] = ffma2(q1.x, p2, acc[px][2]);
                acc[px][3] = ffma2(q1.y, p2, acc[px][3]);
            }
        }
    }
}

// ============================================================================
// conv 64->64 (W_z). Tile 64w x 32h, 8 out-channels per block, 8 px/thread.
// 3-stage x 2-ic cp.async ring (one barrier per 2 channels); FFMA2 inner.
// Epilogue emits zpre (float4 stores) + deterministic BN partial sums.
// grid: (2, 4, NS*8), block: 256, dynamic smem CONVZ_SMEM_B
// ============================================================================
__global__ void __launch_bounds__(256, 2)
convz_kernel(const float* __restrict__ src,   // [NS][KC][IMG]
             const float* __restrict__ Wz,    // [64][64][49] for this layer
             const float* __restrict__ bz,    // [64]
             float* __restrict__ dst)         // [NS][KC][IMG]
{
    extern __shared__ __align__(16) float sdyn[];
    float* s_in  = sdyn;                         // [6][TWORDS]
    float* s_w   = sdyn + CONVZ_SIN_F;           // [6][392]
    float* s_red = s_w + CONVZ_SW_F;             // [8][16]

    const int tid = threadIdx.x;
    const int s   = blockIdx.z >> 3;
    const int ocg = blockIdx.z & 7;
    const int x0  = blockIdx.x * 64;
    const int y0  = blockIdx.y * 32;
    const int tx  = tid & 7;    // col block (8 px wide)
    const int ty  = tid >> 3;   // row 0..31

    const unsigned su_in = (unsigned)__cvta_generic_to_shared(s_in);
    const unsigned su_w  = (unsigned)__cvta_generic_to_shared(s_w);

    int soff[3]; unsigned doff[3];
    tile_slots(tid, x0, y0, soff, doff);

    int wsrc[2]; unsigned wdst[2];
#pragma unroll
    for (int k = 0; k < 2; k++) {
        int i = tid + k * 256;
        if (i < 392) {
            int tap = i >> 3, j = i & 7;
            wsrc[k] = (ocg * 8 + j) * 3136 + tap;   // + ic*49 later
            wdst[k] = (unsigned)(tap * 8 + j) * 4u;
        } else { wsrc[k] = -1; wdst[k] = 0; }
    }

    const float* srcS = src + (size_t)s * CHW;

    unsigned long long acc[8][4];
#pragma unroll
    for (int px = 0; px < 8; px++)
#pragma unroll
        for (int p = 0; p < 4; p++) acc[px][p] = 0ULL;

    // prefetch one stage (2 input channels + their weights), one commit group
    auto prefetch_stage = [&](int st) {
        const int ring = st % 3;
#pragma unroll
        for (int sl = 0; sl < 2; sl++) {
            const int ic = st * 2 + sl;
            unsigned bi = su_in + (unsigned)(ring * 2 + sl) * (TWORDS * 4);
            const float* sp = srcS + ic * IMG;
#pragma unroll
            for (int k = 0; k < 3; k++) {
                if (doff[k] != 0xffffffffu) {
                    int so = soff[k];
                    const float* p = sp + (so < 0 ? 0 : so);
                    int sz = (so < 0) ? 0 : 16;
                    asm volatile("cp.async.cg.shared.global [%0], [%1], 16, %2;"
                                 :: "r"(bi + doff[k]), "l"(p), "r"(sz));
                }
            }
            unsigned bw = su_w + (unsigned)(ring * 2 + sl) * (392 * 4);
#pragma unroll
            for (int k = 0; k < 2; k++) {
                if (wsrc[k] >= 0)
                    asm volatile("cp.async.ca.shared.global [%0], [%1], 4;"
                                 :: "r"(bw + wdst[k]), "l"(Wz + wsrc[k] + ic * 49));
            }
        }
        asm volatile("cp.async.commit_group;");
    };

    prefetch_stage(0);

    for (int st = 0; st < KC / 2; st++) {
        if (st < KC / 2 - 1) {
            prefetch_stage(st + 1);
            asm volatile("cp.async.wait_group 1;");
        } else {
            asm volatile("cp.async.wait_group 0;");
        }
        __syncthreads();

        const int ring = st % 3;
#pragma unroll 1
        for (int sl = 0; sl < 2; sl++) {
            const float* bin = s_in + (size_t)(ring * 2 + sl) * TWORDS;
            const float* bwm = s_w  + (size_t)(ring * 2 + sl) * 392;
            convz_ic_body(bin, bwm, ty, tx, acc);
        }
    }

    // ---- epilogue: float4 zpre stores + deterministic BN partials ----
    const int gy = y0 + ty, gxb = x0 + tx * 8;
    const int warp = tid >> 5, lane = tid & 31;
#pragma unroll
    for (int p = 0; p < 4; p++) {
        int oc0 = ocg * 8 + 2 * p;
        float b0 = bz[oc0], b1 = bz[oc0 + 1];
        float* d0 = dst + ((size_t)s * KC + oc0) * IMG + gy * 128 + gxb;
        float* d1 = d0 + IMG;
        float v0[8], v1[8];
        float s0 = 0.f, s1 = 0.f, q0 = 0.f, q1 = 0.f;
#pragma unroll
        for (int px = 0; px < 8; px++) {
            float u0, u1;
            unpack2(acc[px][p], u0, u1);
            u0 += b0; u1 += b1;
            v0[px] = u0; v1[px] = u1;
            s0 += u0; q0 += u0 * u0;
            s1 += u1; q1 += u1 * u1;
        }
        ((float4*)d0)[0] = make_float4(v0[0], v0[1], v0[2], v0[3]);
        ((float4*)d0)[1] = make_float4(v0[4], v0[5], v0[6], v0[7]);
        ((float4*)d1)[0] = make_float4(v1[0], v1[1], v1[2], v1[3]);
        ((float4*)d1)[1] = make_float4(v1[4], v1[5], v1[6], v1[7]);
#pragma unroll
        for (int o = 16; o; o >>= 1) {
            s0 += __shfl_xor_sync(0xffffffffu, s0, o);
            s1 += __shfl_xor_sync(0xffffffffu, s1, o);
            q0 += __shfl_xor_sync(0xffffffffu, q0, o);
            q1 += __shfl_xor_sync(0xffffffffu, q1, o);
        }
        if (lane == 0) {
            s_red[warp * 16 + p * 4 + 0] = s0;
            s_red[warp * 16 + p * 4 + 1] = s1;
            s_red[warp * 16 + p * 4 + 2] = q0;
            s_red[warp * 16 + p * 4 + 3] = q1;
        }
    }
    __syncthreads();
    if (tid < 16) {
        float t = 0.f;
#pragma unroll
        for (int w = 0; w < 8; w++) t += s_red[w * 16 + tid];
        int p = tid >> 2, j = tid & 3;
        int oc = ocg * 8 + 2 * p + (j & 1);
        int tile = blockIdx.y * 2 + blockIdx.x;           // 0..7
        size_t idx = ((size_t)s * KC + oc) * 8 + tile;
        if (j < 2) g_psum[idx] = t;
        else       g_psq[idx]  = t;
    }
}

// ============================================================================
// conv 1->64 (W_fe / W_enc) fused: out = softshrink(conv(src)+b [+ base])
// cp.async tile + weight load (convz loader), convz_ic_body compute,
// float4 epilogue. grid: (2, 4, NS*8), block: 256
// ============================================================================
__global__ void __launch_bounds__(256, 2)
conv1to64_kernel(const float* __restrict__ src,   // [NS][IMG]
                 const float* __restrict__ W,     // [64][49]
                 const float* __restrict__ b,     // [64]
                 const float* __restrict__ base,  // [NS][KC][IMG] or null
                 float* __restrict__ dst)         // [NS][KC][IMG]
{
    __shared__ __align__(16) float s_in[TWORDS];
    __shared__ __align__(16) float s_w [392];

    const int tid = threadIdx.x;
    const int s   = blockIdx.z >> 3;
    const int ocg = blockIdx.z & 7;
    const int x0  = blockIdx.x * 64;
    const int y0  = blockIdx.y * 32;
    const int tx  = tid & 7;
    const int ty  = tid >> 3;

    const unsigned su_in = (unsigned)__cvta_generic_to_shared(s_in);
    const unsigned su_w  = (unsigned)__cvta_generic_to_shared(s_w);

    int soff[3]; unsigned doff[3];
    tile_slots(tid, x0, y0, soff, doff);

    const float* sp = src + (size_t)s * IMG;
#pragma unroll
    for (int k = 0; k < 3; k++) {
        if (doff[k] != 0xffffffffu) {
            int so = soff[k];
            const float* p = sp + (so < 0 ? 0 : so);
            int sz = (so < 0) ? 0 : 16;
            asm volatile("cp.async.cg.shared.global [%0], [%1], 16, %2;"
                         :: "r"(su_in + doff[k]), "l"(p), "r"(sz));
        }
    }
#pragma unroll
    for (int k = 0; k < 2; k++) {
        int i = tid + k * 256;
        if (i < 392) {
            int tap = i >> 3, j = i & 7;
            asm volatile("cp.async.ca.shared.global [%0], [%1], 4;"
                         :: "r"(su_w + (unsigned)(tap * 8 + j) * 4u),
                            "l"(W + (size_t)(ocg * 8 + j) * 49 + tap));
        }
    }
    asm volatile("cp.async.commit_group;");
    asm volatile("cp.async.wait_group 0;");
    __syncthreads();

    unsigned long long acc[8][4];
#pragma unroll
    for (int px = 0; px < 8; px++)
#pragma unroll
        for (int p = 0; p < 4; p++) acc[px][p] = 0ULL;

    convz_ic_body(s_in, s_w, ty, tx, acc);

    const int gy = y0 + ty, gxb = x0 + tx * 8;
#pragma unroll
    for (int p = 0; p < 4; p++) {
        int oc0 = ocg * 8 + 2 * p;
        float b0 = b[oc0], b1 = b[oc0 + 1];
        size_t o0 = ((size_t)s * KC + oc0) * IMG + gy * 128 + gxb;
        float v0[8], v1[8];
#pragma unroll
        for (int px = 0; px < 8; px++) {
            float u0, u1;
            unpack2(acc[px][p], u0, u1);
            v0[px] = u0 + b0;
            v1[px] = u1 + b1;
        }
        if (base) {
            float4 ba0 = ((const float4*)(base + o0))[0];
            float4 ba1 = ((const float4*)(base + o0))[1];
            float4 bb0 = ((const float4*)(base + o0 + IMG))[0];
            float4 bb1 = ((const float4*)(base + o0 + IMG))[1];
            v0[0]+=ba0.x; v0[1]+=ba0.y; v0[2]+=ba0.z; v0[3]+=ba0.w;
            v0[4]+=ba1.x; v0[5]+=ba1.y; v0[6]+=ba1.z; v0[7]+=ba1.w;
            v1[0]+=bb0.x; v1[1]+=bb0.y; v1[2]+=bb0.z; v1[3]+=bb0.w;
            v1[4]+=bb1.x; v1[5]+=bb1.y; v1[6]+=bb1.z; v1[7]+=bb1.w;
        }
#pragma unroll
        for (int px = 0; px < 8; px++) {
            v0[px] = softshrink_f(v0[px]);
            v1[px] = softshrink_f(v1[px]);
        }
        ((float4*)(dst + o0))[0]       = make_float4(v0[0], v0[1], v0[2], v0[3]);
        ((float4*)(dst + o0))[1]       = make_float4(v0[4], v0[5], v0[6], v0[7]);
        ((float4*)(dst + o0 + IMG))[0] = make_float4(v1[0], v1[1], v1[2], v1[3]);
        ((float4*)(dst + o0 + IMG))[1] = make_float4(v1[4], v1[5], v1[6], v1[7]);
    }
}

// ============================================================================
// conv 64->1 (W_dec / W_last), 3-stage cp.async pipeline over input channels.
// Inner loop on f32x2 pixel pairs (validated xe/xo indexing); weights
// broadcast-packed (R13-validated). Vectorized xin/dst epilogue.
// mode 0: dst = xin - (conv(src)+b);  mode 1: dst = conv(src)+b
// grid: (2, 4, NS), block: 256
// ============================================================================
__global__ void __launch_bounds__(256, 2)
conv64to1_kernel(const float* __restrict__ src,  // [NS][KC][IMG]
                 const float* __restrict__ W,    // [64][49]
                 const float* __restrict__ b,    // [1]
                 const float* __restrict__ xin,  // [NS][IMG] (mode 0)
                 float* __restrict__ dst,        // [NS][IMG]
                 int mode)
{
    __shared__ __align__(16) float s_in[3][TWORDS];
    __shared__ float s_w[3][52];

    const int tid = threadIdx.x;
    const int s   = blockIdx.z;
    const int x0  = blockIdx.x * 64;
    const int y0  = blockIdx.y * 32;
    const int tx  = tid & 7;
    const int ty  = tid >> 3;

    const unsigned su_in = (unsigned)__cvta_generic_to_shared(&s_in[0][0]);
    const unsigned su_w  = (unsigned)__cvta_generic_to_shared(&s_w[0][0]);

    int soff[3]; unsigned doff[3];
    tile_slots(tid, x0, y0, soff, doff);

    unsigned long long acc2[4];
#pragma unroll
    for (int p = 0; p < 4; p++) acc2[p] = 0ULL;

    const float* srcS = src + (size_t)s * CHW;

    for (int ic = -1; ic < KC; ic++) {
        const int nxt = ic + 1;
        if (nxt < KC) {
            unsigned bi = su_in + (unsigned)(nxt % 3) * (TWORDS * 4);
            const float* sp = srcS + nxt * IMG;
#pragma unroll
            for (int k = 0; k < 3; k++) {
                if (doff[k] != 0xffffffffu) {
                    int so = soff[k];
                    const float* p = sp + (so < 0 ? 0 : so);
                    int sz = (so < 0) ? 0 : 16;
                    asm volatile("cp.async.cg.shared.global [%0], [%1], 16, %2;"
                                 :: "r"(bi + doff[k]), "l"(p), "r"(sz));
                }
            }
            if (tid < 49) {
                unsigned bw = su_w + (unsigned)(nxt % 3) * (52 * 4);
                asm volatile("cp.async.ca.shared.global [%0], [%1], 4;"
                             :: "r"(bw + tid * 4), "l"(W + nxt * 49 + tid));
            }
            asm volatile("cp.async.commit_group;");
        }
        if (ic < 0) continue;
        if (nxt < KC) asm volatile("cp.async.wait_group 1;");
        else          asm volatile("cp.async.wait_group 0;");
        __syncthreads();

        const float* bin = &s_in[ic % 3][0];
        const float* bwm = &s_w [ic % 3][0];

#pragma unroll
        for (int ky = 0; ky < 7; ky++) {
            const float4* rp = (const float4*)&bin[(ty + ky) * TSTR + tx * 8];
            float4 a0 = rp[0], a1 = rp[1], a2 = rp[2], a3 = rp[3];
            float row[16];
            row[0]=a0.x; row[1]=a0.y; row[2]=a0.z; row[3]=a0.w;
            row[4]=a1.x; row[5]=a1.y; row[6]=a1.z; row[7]=a1.w;
            row[8]=a2.x; row[9]=a2.y; row[10]=a2.z; row[11]=a2.w;
            row[12]=a3.x; row[13]=a3.y; row[14]=a3.z; row[15]=a3.w;
            unsigned long long xe[7], xo[7];
#pragma unroll
            for (int i = 0; i < 7; i++) {
                xe[i] = pack2(row[2*i],     row[2*i + 1]);
                xo[i] = pack2(row[2*i + 1], row[2*i + 2]);
            }
#pragma unroll
            for (int kx = 0; kx < 7; kx++) {
                float w = bwm[ky * 7 + kx];
                unsigned long long w2 = pack2(w, w);
#pragma unroll
                for (int p = 0; p < 4; p++) {
                    unsigned long long x = (kx & 1)
                        ? xe[((kx + 1) >> 1) + p]
                        : xo[(kx >> 1) + p];
                    acc2[p] = ffma2(w2, x, acc2[p]);
                }
            }
        }
    }

    const float bv = b[0];
    const int gy = y0 + ty, gxb = x0 + tx * 8;
    const size_t o = (size_t)s * IMG + gy * 128 + gxb;
    float v[8];
#pragma unroll
    for (int p = 0; p < 4; p++) {
        float u0, u1;
        unpack2(acc2[p], u0, u1);
        v[2*p]   = u0 + bv;
        v[2*p+1] = u1 + bv;
    }
    if (mode == 0) {
        float4 xa = ((const float4*)(xin + o))[0];
        float4 xbq = ((const float4*)(xin + o))[1];
        v[0] = xa.x  - v[0]; v[1] = xa.y  - v[1];
        v[2] = xa.z  - v[2]; v[3] = xa.w  - v[3];
        v[4] = xbq.x - v[4]; v[5] = xbq.y - v[5];
        v[6] = xbq.z - v[6]; v[7] = xbq.w - v[7];
    }
    ((float4*)(dst + o))[0] = make_float4(v[0], v[1], v[2], v[3]);
    ((float4*)(dst + o))[1] = make_float4(v[4], v[5], v[6], v[7]);
}

// ============================================================================
// Fused BN-finish + BN-normalize + sigmoid + directional GRU scan.
// float4 per thread, 2-deep software pipeline on the band loop.
// grid: CHW/1024 = 1024, block: 256
// ============================================================================
__global__ void scan_kernel(const float* __restrict__ gamma,
                            const float* __restrict__ beta,
                            float* __restrict__ csc, int fwd)
{
    __shared__ float s_mu[NS], s_rs[NS];

    const int c = (int)(((unsigned)blockIdx.x * 1024u) >> 14);   // block-uniform
    if (threadIdx.x < NS) {
        int s = threadIdx.x;
        size_t base = ((size_t)s * KC + c) * 8;
        float sm = 0.f, sq = 0.f;
#pragma unroll
        for (int t = 0; t < 8; t++) {
            sm += g_psum[base + t];
            sq += g_psq [base + t];
        }
        float mu  = sm * (1.f / IMG);
        float var = sq * (1.f / IMG) - mu * mu;
        s_mu[s] = mu;
        s_rs[s] = rsqrtf(var + EPS_BN);
    }
    __syncthreads();

    const float g  = gamma[c];
    const float be = beta[c];
    const size_t p0 = (size_t)blockIdx.x * 1024 + (size_t)threadIdx.x * 4;

    const int s0   = fwd ? 0 : (NS - 1);
    const int step = fwd ? 1 : -1;

    float4 carry = *(const float4*)(g_tmp + (size_t)s0 * CHW + p0);
    *(float4*)(csc + (size_t)s0 * CHW + p0) = carry;

    int s_next = s0 + step;
    float4 zp = *(const float4*)(g_zpre + (size_t)s_next * CHW + p0);
    float4 tm = *(const float4*)(g_tmp  + (size_t)s_next * CHW + p0);

    int s = s_next;
    for (int k = 1; k < NS; k++) {
        const size_t o = (size_t)s * CHW + p0;
        float4 zp_c = zp, tm_c = tm;
        const float mu = s_mu[s], rs = s_rs[s];
        if (k < NS - 1) {
            size_t on = (size_t)(s + step) * CHW + p0;
            zp = *(const float4*)(g_zpre + on);
            tm = *(const float4*)(g_tmp  + on);
        }
        {
            float t = ((zp_c.x - mu) * rs) * g + be;
            float z = __fdividef(1.f, 1.f + __expf(-t));
            carry.x = z * carry.x + (1.f - z) * tm_c.x;
        }
        {
            float t = ((zp_c.y - mu) * rs) * g + be;
            float z = __fdividef(1.f, 1.f + __expf(-t));
            carry.y = z * carry.y + (1.f - z) * tm_c.y;
        }
        {
            float t = ((zp_c.z - mu) * rs) * g + be;
            float z = __fdividef(1.f, 1.f + __expf(-t));
            carry.z = z * carry.z + (1.f - z) * tm_c.z;
        }
        {
            float t = ((zp_c.w - mu) * rs) * g + be;
            float z = __fdividef(1.f, 1.f + __expf(-t));
            carry.w = z * carry.w + (1.f - z) * tm_c.w;
        }
        *(float4*)(csc + o) = carry;
        s += step;
    }
}

// ============================================================================
extern "C" void kernel_launch(void* const* d_in, const int* in_sizes, int n_in,
                              void* d_out, int out_size)
{
    const float* inputs = (const float*)d_in[0];
    const float* W_fe   = (const float*)d_in[1];
    const float* b_fe   = (const float*)d_in[2];
    const float* W_enc  = (const float*)d_in[3];
    const float* b_enc  = (const float*)d_in[4];
    const float* W_dec  = (const float*)d_in[5];
    const float* b_dec  = (const float*)d_in[6];
    const float* W_last = (const float*)d_in[7];
    const float* b_last = (const float*)d_in[8];
    const float* W_z    = (const float*)d_in[9];
    const float* b_z    = (const float*)d_in[10];
    const float* bn_g   = (const float*)d_in[11];
    const float* bn_b   = (const float*)d_in[12];
    (void)in_sizes; (void)n_in;

    // allow >48KB dynamic smem for convz (host attribute set; capture-legal)
    cudaFuncSetAttribute((const void*)convz_kernel,
                         cudaFuncAttributeMaxDynamicSharedMemorySize,
                         CONVZ_SMEM_B);

    float *p_res, *p_tmp, *p_zpre, *p_outsc, *p_cscs;
    cudaGetSymbolAddress((void**)&p_res,   g_res);
    cudaGetSymbolAddress((void**)&p_tmp,   g_tmp);
    cudaGetSymbolAddress((void**)&p_zpre,  g_zpre);
    cudaGetSymbolAddress((void**)&p_outsc, g_outsc);
    cudaGetSymbolAddress((void**)&p_cscs,  g_cscsc);

    const long long CSC_N = (long long)NS * CHW;   // 32,505,856
    const long long OUT_N = (long long)NS * IMG;   //    507,904
    float* csc;
    float* outp;
    if ((long long)out_size >= CSC_N + OUT_N) {
        csc  = (float*)d_out;
        outp = (float*)d_out + CSC_N;
    } else if ((long long)out_size >= CSC_N) {
        csc  = (float*)d_out;
        outp = p_outsc;
    } else {
        csc  = p_cscs;
        outp = (float*)d_out;
    }

    dim3 blk(256);
    dim3 g64(2, 4, NS * 8);
    dim3 g1 (2, 4, NS);

    // csc = softshrink(conv_fe(x) + b_fe)
    conv1to64_kernel<<<g64, blk>>>(inputs, W_fe, b_fe, nullptr, csc);

    for (int it = 0; it < 3; it++) {
        // res = x - (conv_dec(csc) + b_dec)
        conv64to1_kernel<<<g1, blk>>>(csc, W_dec + it * 3136, b_dec + it,
                                      inputs, p_res, 0);
        // tmp = softshrink(csc + conv_enc(res) + b_enc)
        conv1to64_kernel<<<g64, blk>>>(p_res, W_enc + it * 3136,
                                       b_enc + it * 64, csc, p_tmp);
        // zpre = conv_z(tmp) + b_z   (also emits BN partial sums)
        convz_kernel<<<g64, blk, CONVZ_SMEM_B>>>(p_tmp,
                                   W_z + (size_t)it * 64 * 64 * 49,
                                   b_z + it * 64, p_zpre);
        // fused BN-finish + BN + sigmoid + directional scan -> csc
        scan_kernel<<<CHW / 1024, 256>>>(bn_g + it * 64, bn_b + it * 64,
                                         csc, (it % 2 == 0) ? 1 : 0);
    }

    // outputs = conv_last(csc) + b_last
    conv64to1_kernel<<<g1, blk>>>(csc, W_last, b_last, nullptr, outp, 1);
}